// round 1
// baseline (speedup 1.0000x reference)
#include <cuda_runtime.h>
#include <cuda_bf16.h>
#include <cstdint>

// Problem constants
#define MULV    64
#define TILE_Z  32
#define NTHREADS 256

// Folded constants
#define C000f 0.7071067811865476f
#define C110f 0.4082482904638631f
#define C011f 0.7071067811865476f
#define C101f 0.7071067811865476f

// Packed weights: [c(2)][n(128)][kk(8)][tig(4)] float2 = {tf32(w[kk*8+tig][n]*0.125), tf32(w[kk*8+tig+4][n]*0.125)}
__device__ float2 g_wpk[2 * 128 * 8 * 4];
// Folded tp_w: [0]=C000*wA, [64]=C110*wD, [128]=C011*wB, [192]=C101*wC
__device__ float g_tpw[256];

__device__ __forceinline__ unsigned tf32_bits(float f) {
    unsigned r;
    asm("cvt.rna.tf32.f32 %0, %1;" : "=r"(r) : "f"(f));
    return r;
}

__global__ void pack_kernel(const float* __restrict__ tp_w,
                            const float* __restrict__ w0,
                            const float* __restrict__ w1) {
    int t = blockIdx.x * blockDim.x + threadIdx.x;
    if (t < 8192) {
        // t = c*4096 + n*32 + kk*4 + tig  (matches g_wpk layout exactly)
        int c   = t >> 12;
        int rem = t & 4095;
        int n   = rem >> 5;
        int kk  = (rem >> 2) & 7;
        int tig = rem & 3;
        const float* w = c ? w1 : w0;
        int u0 = kk * 8 + tig;
        float2 v;
        v.x = __uint_as_float(tf32_bits(w[u0 * 128 + n] * 0.125f));
        v.y = __uint_as_float(tf32_bits(w[(u0 + 4) * 128 + n] * 0.125f));
        g_wpk[t] = v;
    } else if (t < 8192 + 64) {
        int u = t - 8192;
        g_tpw[u]       = C000f * tp_w[u];
        g_tpw[64 + u]  = C110f * tp_w[192 + u];
        g_tpw[128 + u] = C011f * tp_w[64 + u];
        g_tpw[192 + u] = C101f * tp_w[128 + u];
    }
}

// smem layout (floats):
//   mids: 4 channels * 32 z * 68 (stride)  = 8704   (tf32-rounded A operands)
//   outs: 32 z * 516 (stride)              = 16512  (fp32 output staging)
//   ys:   32 z * 4                         = 128
#define MID_STRIDE 68
#define MID_CH     (TILE_Z * MID_STRIDE)   // 2176
#define OUT_STRIDE 516
#define SMEM_FLOATS (4 * MID_CH + TILE_Z * OUT_STRIDE + TILE_Z * 4)

__global__ void __launch_bounds__(NTHREADS, 2)
tpmm_kernel(const float* __restrict__ x, const float* __restrict__ y,
            float* __restrict__ out) {
    extern __shared__ float smem[];
    float* mids = smem;
    float* outs = smem + 4 * MID_CH;
    float* ys   = smem + 4 * MID_CH + TILE_Z * OUT_STRIDE;

    const int tid = threadIdx.x;
    const int z0  = blockIdx.x * TILE_Z;

    if (tid < TILE_Z * 4) ys[tid] = y[(size_t)z0 * 4 + tid];
    __syncthreads();

    // ---- Phase 1: compute mid (fp32), round to tf32, store to smem ----
    #pragma unroll
    for (int j = 0; j < 8; j++) {
        int p = tid + NTHREADS * j;       // 0..2047
        int z = p >> 6;
        int u = p & 63;
        const float* xp = x + (size_t)(z0 + z) * 256;
        float x0v = xp[u];
        float xa  = xp[64 + 3 * u];
        float xb  = xp[65 + 3 * u];
        float xc  = xp[66 + 3 * u];
        float y0v = ys[z * 4 + 0];
        float ya  = ys[z * 4 + 1];
        float yb  = ys[z * 4 + 2];
        float yc  = ys[z * 4 + 3];
        float tA = g_tpw[u];
        float tD = g_tpw[64 + u];
        float tB = g_tpw[128 + u];
        float tC = g_tpw[192 + u];

        float m0  = tA * x0v * y0v + tD * (xa * ya + xb * yb + xc * yc);
        float m1a = tB * x0v * ya + tC * xa * y0v;
        float m1b = tB * x0v * yb + tC * xb * y0v;
        float m1c = tB * x0v * yc + tC * xc * y0v;

        int base = z * MID_STRIDE + u;
        mids[base]              = __uint_as_float(tf32_bits(m0));
        mids[MID_CH + base]     = __uint_as_float(tf32_bits(m1a));
        mids[2 * MID_CH + base] = __uint_as_float(tf32_bits(m1b));
        mids[3 * MID_CH + base] = __uint_as_float(tf32_bits(m1c));
    }
    __syncthreads();

    // ---- Phase 2: per-warp GEMM tile via mma.sync m16n8k8 tf32 ----
    const int warp = tid >> 5;
    const int lane = tid & 31;
    const int gID  = lane >> 2;   // 0..7
    const int tig  = lane & 3;    // 0..3
    const int ch   = warp >> 1;   // 0..3 (channel)
    const int zh   = warp & 1;    // 0..1 (M half: 16 rows each)
    const int c01  = (ch == 0) ? 0 : 1;

    float acc[16][4];
    #pragma unroll
    for (int nt = 0; nt < 16; nt++) {
        acc[nt][0] = 0.f; acc[nt][1] = 0.f; acc[nt][2] = 0.f; acc[nt][3] = 0.f;
    }

    const float* mbase = mids + ch * MID_CH + (zh * 16 + gID) * MID_STRIDE + tig;

    #pragma unroll
    for (int kk = 0; kk < 8; kk++) {
        unsigned a0 = __float_as_uint(mbase[kk * 8]);
        unsigned a2 = __float_as_uint(mbase[kk * 8 + 4]);
        unsigned a1 = __float_as_uint(mbase[kk * 8 + 8 * MID_STRIDE]);
        unsigned a3 = __float_as_uint(mbase[kk * 8 + 4 + 8 * MID_STRIDE]);
        const float2* wb = g_wpk + c01 * 4096 + gID * 32 + kk * 4 + tig;
        #pragma unroll
        for (int nt = 0; nt < 16; nt++) {
            float2 b = wb[nt * 256];   // n = nt*8 + gID
            unsigned b0 = __float_as_uint(b.x);
            unsigned b1 = __float_as_uint(b.y);
            asm volatile(
                "mma.sync.aligned.m16n8k8.row.col.f32.tf32.tf32.f32 "
                "{%0,%1,%2,%3}, {%4,%5,%6,%7}, {%8,%9}, {%0,%1,%2,%3};"
                : "+f"(acc[nt][0]), "+f"(acc[nt][1]),
                  "+f"(acc[nt][2]), "+f"(acc[nt][3])
                : "r"(a0), "r"(a1), "r"(a2), "r"(a3), "r"(b0), "r"(b1));
        }
    }

    // ---- Epilogue: stage interleaved layout in smem ----
    {
        int r0 = zh * 16 + gID;
        int r1 = r0 + 8;
        if (ch == 0) {
            #pragma unroll
            for (int nt = 0; nt < 16; nt++) {
                int col = nt * 8 + 2 * tig;
                outs[r0 * OUT_STRIDE + col]     = acc[nt][0];
                outs[r0 * OUT_STRIDE + col + 1] = acc[nt][1];
                outs[r1 * OUT_STRIDE + col]     = acc[nt][2];
                outs[r1 * OUT_STRIDE + col + 1] = acc[nt][3];
            }
        } else {
            int k3 = ch - 1;
            #pragma unroll
            for (int nt = 0; nt < 16; nt++) {
                int n = nt * 8 + 2 * tig;
                outs[r0 * OUT_STRIDE + 128 + n * 3 + k3]       = acc[nt][0];
                outs[r0 * OUT_STRIDE + 128 + (n + 1) * 3 + k3] = acc[nt][1];
                outs[r1 * OUT_STRIDE + 128 + n * 3 + k3]       = acc[nt][2];
                outs[r1 * OUT_STRIDE + 128 + (n + 1) * 3 + k3] = acc[nt][3];
            }
        }
    }
    __syncthreads();

    // ---- Coalesced float4 store to global ----
    #pragma unroll
    for (int i = tid; i < TILE_Z * 128; i += NTHREADS) {
        int r  = i >> 7;
        int cc = (i & 127) << 2;
        float4 v = *reinterpret_cast<const float4*>(&outs[r * OUT_STRIDE + cc]);
        *reinterpret_cast<float4*>(&out[(size_t)(z0 + r) * 512 + cc]) = v;
    }
}

extern "C" void kernel_launch(void* const* d_in, const int* in_sizes, int n_in,
                              void* d_out, int out_size) {
    const float* x    = (const float*)d_in[0];
    const float* y    = (const float*)d_in[1];
    const float* tp_w = (const float*)d_in[2];
    const float* w0   = (const float*)d_in[3];
    const float* w1   = (const float*)d_in[4];
    float* out        = (float*)d_out;

    int Z = in_sizes[0] / 256;

    pack_kernel<<<(8192 + 64 + 255) / 256, 256>>>(tp_w, w0, w1);

    const int smem_bytes = SMEM_FLOATS * 4;
    cudaFuncSetAttribute(tpmm_kernel,
                         cudaFuncAttributeMaxDynamicSharedMemorySize, smem_bytes);
    tpmm_kernel<<<Z / TILE_Z, NTHREADS, smem_bytes>>>(x, y, out);
}

// round 3
// speedup vs baseline: 1.9767x; 1.9767x over previous
#include <cuda_runtime.h>
#include <cuda_fp16.h>
#include <cstdint>

#define TILE_Z 64
#define NTH    512

#define C000f 0.7071067811865476f
#define C110f 0.4082482904638631f
#define C011f 0.7071067811865476f
#define C101f 0.7071067811865476f

// B fragments, fp16-packed, 0.125-scaled: [wsel(2)][kk(4)][n(128)][tig(4)] uint2
//   .x = half2(w[kk*16+2t][n], w[kk*16+2t+1][n]), .y = half2(w[kk*16+2t+8][n], w[kk*16+2t+9][n])
__device__ uint2 g_wt[4096];
// Folded tp_w: [0]=C000*wA, [64]=C110*wD, [128]=C011*wB, [192]=C101*wC
__device__ float g_tpw[256];

__device__ __forceinline__ uint32_t smem_u32(const void* p) {
    uint32_t a;
    asm("{ .reg .u64 t; cvta.to.shared.u64 t, %1; cvt.u32.u64 %0, t; }" : "=r"(a) : "l"(p));
    return a;
}
__device__ __forceinline__ uint32_t h2u(float a, float b) {
    __half2 h = __floats2half2_rn(a, b);
    return *reinterpret_cast<uint32_t*>(&h);
}
__device__ __forceinline__ void ldsm_x4(uint32_t* r, uint32_t addr) {
    asm volatile("ldmatrix.sync.aligned.m8n8.x4.shared.b16 {%0,%1,%2,%3}, [%4];"
        : "=r"(r[0]), "=r"(r[1]), "=r"(r[2]), "=r"(r[3]) : "r"(addr));
}
__device__ __forceinline__ void mma_f16(float* c, const uint32_t* a, uint2 b) {
    asm volatile("mma.sync.aligned.m16n8k16.row.col.f32.f16.f16.f32 "
        "{%0,%1,%2,%3}, {%4,%5,%6,%7}, {%8,%9}, {%0,%1,%2,%3};"
        : "+f"(c[0]), "+f"(c[1]), "+f"(c[2]), "+f"(c[3])
        : "r"(a[0]), "r"(a[1]), "r"(a[2]), "r"(a[3]), "r"(b.x), "r"(b.y));
}

// ---------------- pack kernel ----------------
__global__ void pack_kernel(const float* __restrict__ tp_w,
                            const float* __restrict__ w0,
                            const float* __restrict__ w1) {
    int t = blockIdx.x * blockDim.x + threadIdx.x;
    if (t < 4096) {
        int tig  = t & 3;
        int n    = (t >> 2) & 127;
        int kk   = (t >> 9) & 3;
        int wsel = t >> 11;
        const float* w = wsel ? w1 : w0;
        int K0 = kk * 16 + 2 * tig;
        uint2 v;
        v.x = h2u(w[K0 * 128 + n] * 0.125f,       w[(K0 + 1) * 128 + n] * 0.125f);
        v.y = h2u(w[(K0 + 8) * 128 + n] * 0.125f, w[(K0 + 9) * 128 + n] * 0.125f);
        g_wt[t] = v;
    } else if (t < 4096 + 64) {
        int u = t - 4096;
        g_tpw[u]       = C000f * tp_w[u];
        g_tpw[64 + u]  = C110f * tp_w[192 + u];
        g_tpw[128 + u] = C011f * tp_w[64 + u];
        g_tpw[192 + u] = C101f * tp_w[128 + u];
    }
}

// ---------------- main kernel ----------------
// Dynamic smem (36,864 B): A tile as half[256 rows][72] (144B row stride, 64 valid k)
// Epilogue reuses the same region as float stage[16][516].
#define A_ROW_H 72
#define STG_STRIDE 516
#define DSM_BYTES (256 * A_ROW_H * 2)

__global__ void __launch_bounds__(NTH, 1)
tpmm_kernel(const float* __restrict__ x, const float* __restrict__ y,
            float* __restrict__ out) {
    extern __shared__ __align__(128) char dsm[];
    __half* A   = (__half*)dsm;
    float* stage = (float*)dsm;
    __shared__ float s_y[TILE_Z * 4];
    __shared__ float s_tpw[256];

    const int tid = threadIdx.x;
    const int z0  = blockIdx.x * TILE_Z;

    if (tid < TILE_Z * 4) s_y[tid] = y[(size_t)z0 * 4 + tid];
    if (tid < 256) s_tpw[tid] = g_tpw[tid];
    __syncthreads();

    // ---- Phase 1: compute mids (fp32), pack to half2, STS.64 into A rows ----
    #pragma unroll
    for (int it = 0; it < (TILE_Z * 16) / NTH; it++) {
        int task = tid + NTH * it;        // 0..1023
        int z = task >> 4;
        int q = task & 15;                // u quad: u = 4q..4q+3
        const float* xp = x + (size_t)(z0 + z) * 256;
        float4 X0 = *(const float4*)(xp + 4 * q);
        const float4* xq = (const float4*)(xp + 64 + 12 * q);
        float4 P0 = xq[0], P1 = xq[1], P2 = xq[2];
        float y0v = s_y[4 * z], ya = s_y[4 * z + 1], yb = s_y[4 * z + 2], yc = s_y[4 * z + 3];
        float4 tA = *(const float4*)(s_tpw + 4 * q);
        float4 tD = *(const float4*)(s_tpw + 64 + 4 * q);
        float4 tB = *(const float4*)(s_tpw + 128 + 4 * q);
        float4 tC = *(const float4*)(s_tpw + 192 + 4 * q);

        float x0a[4] = {X0.x, X0.y, X0.z, X0.w};
        float xaa[4] = {P0.x, P0.w, P1.z, P2.y};
        float xba[4] = {P0.y, P1.x, P1.w, P2.z};
        float xca[4] = {P0.z, P1.y, P2.x, P2.w};
        float tAa[4] = {tA.x, tA.y, tA.z, tA.w};
        float tDa[4] = {tD.x, tD.y, tD.z, tD.w};
        float tBa[4] = {tB.x, tB.y, tB.z, tB.w};
        float tCa[4] = {tC.x, tC.y, tC.z, tC.w};

        float m0[4], ma[4], mb[4], mc[4];
        #pragma unroll
        for (int j = 0; j < 4; j++) {
            m0[j] = tAa[j] * x0a[j] * y0v
                  + tDa[j] * (xaa[j] * ya + xba[j] * yb + xca[j] * yc);
            float tb = tBa[j] * x0a[j];
            float tc = tCa[j] * y0v;
            ma[j] = tb * ya + tc * xaa[j];
            mb[j] = tb * yb + tc * xba[j];
            mc[j] = tb * yc + tc * xca[j];
        }
        uint2 H0 = make_uint2(h2u(m0[0], m0[1]), h2u(m0[2], m0[3]));
        uint2 HA = make_uint2(h2u(ma[0], ma[1]), h2u(ma[2], ma[3]));
        uint2 HB = make_uint2(h2u(mb[0], mb[1]), h2u(mb[2], mb[3]));
        uint2 HC = make_uint2(h2u(mc[0], mc[1]), h2u(mc[2], mc[3]));

        __half* rp = A + (size_t)z * A_ROW_H + 4 * q;
        *(uint2*)(rp)                    = H0;   // rows   0.. 63 : mid0
        *(uint2*)(rp +  64 * A_ROW_H)    = HA;   // rows  64..127 : mid1 k=0
        *(uint2*)(rp + 128 * A_ROW_H)    = HB;   // rows 128..191 : mid1 k=1
        *(uint2*)(rp + 192 * A_ROW_H)    = HC;   // rows 192..255 : mid1 k=2
    }
    __syncthreads();

    // ---- Phase 2: per-warp GEMM. warp = (mq = channel, nq = 32-col quarter) ----
    const int warp = tid >> 5;
    const int lane = tid & 31;
    const int gID  = lane >> 2;
    const int tig  = lane & 3;
    const int mq   = warp >> 2;   // 0..3 -> channel (row block of 64)
    const int nq   = warp & 3;    // 0..3 -> N quarter

    float acc[4][4][4];
    #pragma unroll
    for (int mt = 0; mt < 4; mt++)
        #pragma unroll
        for (int nt = 0; nt < 4; nt++)
            #pragma unroll
            for (int j = 0; j < 4; j++) acc[mt][nt][j] = 0.f;

    // ldmatrix per-lane base: sub = lane>>3 (0..3): rowoff = (sub&1)*8 + (lane&7), coloff = (sub>>1)*16B
    const uint32_t a_base = smem_u32(A)
        + (uint32_t)((mq * 64 + ((lane >> 3) & 1) * 8 + (lane & 7)) * (A_ROW_H * 2))
        + (uint32_t)((lane >> 4) * 16);
    const uint2* wb = g_wt + (mq ? 2048 : 0) + nq * 128 + gID * 4 + tig;

    #pragma unroll
    for (int kk = 0; kk < 4; kk++) {
        uint32_t afr[4][4];
        #pragma unroll
        for (int mt = 0; mt < 4; mt++)
            ldsm_x4(afr[mt], a_base + (uint32_t)(mt * 16 * A_ROW_H * 2 + kk * 32));
        uint2 bfr[4];
        #pragma unroll
        for (int nt = 0; nt < 4; nt++) bfr[nt] = wb[kk * 512 + nt * 32];
        #pragma unroll
        for (int mt = 0; mt < 4; mt++)
            #pragma unroll
            for (int nt = 0; nt < 4; nt++)
                mma_f16(acc[mt][nt], afr[mt], bfr[nt]);
    }

    // ---- Epilogue: 4 chunks of 16 z-rows (chunk c = m-tile c), staged in smem ----
    #pragma unroll
    for (int c = 0; c < 4; c++) {
        __syncthreads();   // A reads done (c==0) / previous copy-out done
        {
            float* r0 = stage + (size_t)gID * STG_STRIDE;
            float* r1 = stage + (size_t)(gID + 8) * STG_STRIDE;
            if (mq == 0) {
                #pragma unroll
                for (int nt = 0; nt < 4; nt++) {
                    int col = nq * 32 + nt * 8 + 2 * tig;
                    *(float2*)(r0 + col) = make_float2(acc[c][nt][0], acc[c][nt][1]);
                    *(float2*)(r1 + col) = make_float2(acc[c][nt][2], acc[c][nt][3]);
                }
            } else {
                int k3 = mq - 1;
                #pragma unroll
                for (int nt = 0; nt < 4; nt++) {
                    int n = nq * 32 + nt * 8 + 2 * tig;
                    int o = 128 + 3 * n + k3;
                    r0[o]     = acc[c][nt][0];
                    r0[o + 3] = acc[c][nt][1];
                    r1[o]     = acc[c][nt][2];
                    r1[o + 3] = acc[c][nt][3];
                }
            }
        }
        __syncthreads();
        #pragma unroll
        for (int j = 0; j < (16 * 128) / NTH; j++) {
            int i  = tid + NTH * j;
            int s  = i >> 7;
            int cc = (i & 127) << 2;
            float4 v = *(const float4*)(stage + (size_t)s * STG_STRIDE + cc);
            *(float4*)(out + (size_t)(z0 + c * 16 + s) * 512 + cc) = v;
        }
    }
}

extern "C" void kernel_launch(void* const* d_in, const int* in_sizes, int n_in,
                              void* d_out, int out_size) {
    const float* x    = (const float*)d_in[0];
    const float* y    = (const float*)d_in[1];
    const float* tp_w = (const float*)d_in[2];
    const float* w0   = (const float*)d_in[3];
    const float* w1   = (const float*)d_in[4];
    float* out        = (float*)d_out;

    int Z = in_sizes[0] / 256;

    pack_kernel<<<(4096 + 64 + 255) / 256, 256>>>(tp_w, w0, w1);
    tpmm_kernel<<<Z / TILE_Z, NTH, DSM_BYTES>>>(x, y, out);
}